// round 15
// baseline (speedup 1.0000x reference)
#include <cuda_runtime.h>
#include <math.h>

typedef unsigned long long ull;

#define Bn  64
#define Tn  128
#define En  300
#define Hn  256
#define G4  1024
#define G2  512
#define WHH_S 264     // w row stride: 2 khalf blocks of 132 floats
#define H_S   260     // h row stride

// ---------------- device scratch ----------------
__device__ float g_xproj[2][(size_t)Bn*Tn*G4];   // [dir][(b*T+t)*1024 + u*4 + gate]
__device__ float g_hbuf[2][2][Bn*Hn];            // [dir][parity][b*256 + u]
__device__ float g_pooled[Bn*G2];
__device__ float g_act0[Bn*G2];
__device__ float g_act1[Bn*G2];
__device__ __align__(128) unsigned g_flags[2][4][32];  // one 128B line per (dir,bq)

// ---------------- packed f32x2 helpers ----------------
__device__ __forceinline__ void fma2(ull& d, ull a, ull b){
    asm("fma.rn.f32x2 %0, %1, %2, %0;" : "+l"(d) : "l"(a), "l"(b));
}
__device__ __forceinline__ float hadd2(ull v){
    float a, b;
    asm("mov.b64 {%0, %1}, %2;" : "=f"(a), "=f"(b) : "l"(v));
    return a + b;
}
__device__ __forceinline__ ull pack2(float lo, float hi){
    ull r;
    asm("mov.b64 %0, {%1, %2};" : "=l"(r) : "f"(lo), "f"(hi));
    return r;
}
__device__ __forceinline__ void unpack2(float& lo, float& hi, ull v){
    asm("mov.b64 {%0, %1}, %2;" : "=f"(lo), "=f"(hi) : "l"(v));
}
__device__ __forceinline__ void ldsv2(ull& a, ull& b, unsigned addr){
    asm volatile("ld.shared.v2.b64 {%0, %1}, [%2];" : "=l"(a), "=l"(b) : "r"(addr));
}
__device__ __forceinline__ void named_bar(int id){
    asm volatile("bar.sync %0, 128;" :: "r"(id) : "memory");
}

// ---------------- tiny kernels: reset + pad (launch-order shim for ncu) ----------------
__global__ void reset_kernel(){
    if (threadIdx.x < 2*4*32)
        ((unsigned*)g_flags)[threadIdx.x] = 0u;
}
__global__ void pad_kernel(){}

// ---------------- kernel 1: gathered input projection GEMM (unchanged) ----------------
__global__ void __launch_bounds__(256,2) proj_kernel(
    const int* __restrict__ sentence, const float* __restrict__ emb,
    const float* __restrict__ wf, const float* __restrict__ wb,
    const float* __restrict__ bihf, const float* __restrict__ bhhf,
    const float* __restrict__ bihb, const float* __restrict__ bhhb)
{
    __shared__ __align__(16) float Asm[32*130];
    __shared__ __align__(16) float Bsm[32*130];
    __shared__ int tok[128];
    int tid = threadIdx.x;
    int rowbase = blockIdx.y * 128;
    int colbase = blockIdx.x * 128;
    int dir = colbase >> 10;
    const float* wsrc = dir ? wb : wf;
    if (tid < 128) tok[tid] = sentence[rowbase + tid];
    __syncthreads();

    int tx = tid & 15, ty = tid >> 4;
    ull acc[4][8];
    #pragma unroll
    for (int i = 0; i < 4; i++)
        #pragma unroll
        for (int m = 0; m < 8; m++) acc[i][m] = 0ull;

    for (int k0 = 0; k0 < 320; k0 += 32) {
        #pragma unroll
        for (int it = 0; it < 16; ++it) {
            int idx = tid + it * 256;
            int kk = idx & 31, r = idx >> 5;
            int k = k0 + kk;
            Asm[kk*130 + r] = (k < En) ? emb[(size_t)tok[r] * En + k] : 0.f;
        }
        #pragma unroll
        for (int it = 0; it < 16; ++it) {
            int idx = tid + it * 256;
            int kk = idx & 31, j = idx >> 5;
            int k = k0 + kk;
            int jg = (colbase + j) & 1023;
            Bsm[kk*130 + j] = (k < En) ? wsrc[jg * En + k] : 0.f;
        }
        __syncthreads();
        #pragma unroll 4
        for (int kk = 0; kk < 32; ++kk) {
            const float* arow = &Asm[kk*130 + ty*8];
            const float* brow = &Bsm[kk*130 + tx];
            ull ap[4];
            #pragma unroll
            for (int i = 0; i < 4; i++) ap[i] = *(const ull*)(arow + 2*i);
            #pragma unroll
            for (int m = 0; m < 8; m++) {
                float bv = brow[m*16];
                ull bb = pack2(bv, bv);
                #pragma unroll
                for (int i = 0; i < 4; i++) fma2(acc[i][m], ap[i], bb);
            }
        }
        __syncthreads();
    }
    const float* bih = dir ? bihb : bihf;
    const float* bhh = dir ? bhhb : bhhf;
    float* outp = g_xproj[dir];
    #pragma unroll
    for (int m = 0; m < 8; m++) {
        int jg = (colbase + tx + m*16) & 1023;
        int u = jg & 255, g = jg >> 8;
        float bsum = bih[jg] + bhh[jg];
        #pragma unroll
        for (int i = 0; i < 4; i++) {
            float lo, hi;
            unpack2(lo, hi, acc[i][m]);
            int r0 = rowbase + ty*8 + 2*i;
            outp[(size_t)r0 * G4 + u*4 + g]       = lo + bsum;
            outp[(size_t)(r0+1) * G4 + u*4 + g]   = hi + bsum;
        }
    }
}

// ---------------- kernel 2: dual-direction BiLSTM recurrence ----------------
// 128 blocks = bq(4) x ubk(32). Threads 0-127: dir0, 128-255: dir1.
// Sync per (dir,bq): 32 per-block FLAGS in one 128B line. Producer posts
// step+1 via st.release to its own word (no atomic drain); every consumer
// warp polls all 32 flags itself (lane i -> word i, one wavefront) and
// spins on __all_sync — no pre-copy named_bar needed.
__global__ void __launch_bounds__(256,1) recur_kernel(
    const float* __restrict__ whh_f, const float* __restrict__ whh_b,
    const int* __restrict__ text_len)
{
    extern __shared__ __align__(16) float dyn[];
    // layout per half: w_sm[32*264], h_sm[16*260]
    int bx  = blockIdx.x;
    int bq  = bx >> 5;
    int ubk = bx & 31;               // units ubk*8 .. +7
    int tid = threadIdx.x;
    int half = tid >> 7;             // dir
    int htid = tid & 127;
    int lane = tid & 31;
    int bl    = htid & 7;
    int khalf = (htid >> 3) & 1;
    int ul    = htid >> 4;           // 0..7
    int bsel = bq*16 + bl + khalf*8; // owned batch
    int u = ubk*8 + ul;

    float* wsm = dyn + half * (32*WHH_S);
    float* hsm = dyn + 2*(32*WHH_S) + half * (16*H_S);

    const float* whh = half ? whh_b : whh_f;
    // stage w rows (8 units x 4 gates) x 256, khalf-blocked: [r][kh*132 + kk]
    #pragma unroll 2
    for (int r = 0; r < 32; ++r) {
        int ul2 = r >> 2, g = r & 3;
        for (int k = htid; k < Hn; k += 128) {
            int kh = k >> 7, kk = k & 127;
            wsm[r*WHH_S + kh*132 + kk] = whh[(size_t)(g*Hn + ubk*8 + ul2) * Hn + k];
        }
    }
    __syncthreads();

    unsigned h0_addr = (unsigned)__cvta_generic_to_shared(hsm + bl*H_S       + khalf*128);
    unsigned h1_addr = (unsigned)__cvta_generic_to_shared(hsm + (bl+8)*H_S   + khalf*128);
    unsigned w_addr  = (unsigned)__cvta_generic_to_shared(wsm + (ul*4)*WHH_S + khalf*132);

    float c_state = 0.f, pooled = 0.f;
    int len = text_len[bsel];
    const float* xp = g_xproj[half];
    unsigned* flag_line = &g_flags[half][bq][0];      // 32 words, one line
    unsigned* my_flag   = &g_flags[half][bq][ubk];
    int barid = 1 + half;

    for (int step = 0; step < Tn; ++step) {
        int tpos = half ? (Tn - 1 - step) : step;
        float4 gx = *(const float4*)(xp + ((size_t)bsel*Tn + tpos)*G4 + u*4);
        float g0 = gx.x, g1 = gx.y, g2 = gx.z, g3 = gx.w;

        if (step > 0) {
            // ---- every warp polls all 32 group flags (lane i -> word i) ----
            unsigned v;
            do {
                asm volatile("ld.acquire.gpu.global.u32 %0, [%1];"
                             : "=r"(v) : "l"(flag_line + lane) : "memory");
            } while (!__all_sync(0xffffffffu, v >= (unsigned)step));
            // ---- copy this half's 16 h rows (16 x 256) into smem ----
            const float* hsrc = g_hbuf[half][(step + 1) & 1] + (size_t)bq*16*Hn;
            #pragma unroll
            for (int q = 0; q < 8; q++) {
                int idx = htid + q*128;
                int row = idx >> 6, c4 = idx & 63;
                float4 vv = __ldcg((const float4*)(hsrc + row*Hn + c4*4));
                *(float4*)&hsm[row*H_S + c4*4] = vv;
            }
            named_bar(barid);
            // ---- partial gate dots: 2 batches x 4 gates over 128 k ----
            ull accA[4][2], accB[4][2];
            #pragma unroll
            for (int g = 0; g < 4; g++) {
                accA[g][0] = accA[g][1] = 0ull;
                accB[g][0] = accB[g][1] = 0ull;
            }
            #pragma unroll 8
            for (int kk = 0; kk < 128; kk += 4) {
                ull ha0, ha1, hb0, hb1;
                ldsv2(ha0, ha1, h0_addr + kk*4);
                ldsv2(hb0, hb1, h1_addr + kk*4);
                #pragma unroll
                for (int g = 0; g < 4; g++) {
                    ull w01, w23;
                    ldsv2(w01, w23, w_addr + (unsigned)(g*WHH_S*4) + kk*4);
                    fma2(accA[g][0], w01, ha0); fma2(accA[g][1], w23, ha1);
                    fma2(accB[g][0], w01, hb0); fma2(accB[g][1], w23, hb1);
                }
            }
            // ---- combine khalf partials: own batch + partner's other-batch ----
            #pragma unroll
            for (int g = 0; g < 4; g++) {
                float sA = hadd2(accA[g][0]) + hadd2(accA[g][1]);   // batch bl
                float sB = hadd2(accB[g][0]) + hadd2(accB[g][1]);   // batch bl+8
                float own = khalf ? sB : sA;
                float oth = khalf ? sA : sB;
                float full = own + __shfl_xor_sync(0xffffffffu, oth, 8);
                if (g == 0) g0 += full;
                else if (g == 1) g1 += full;
                else if (g == 2) g2 += full;
                else g3 += full;
            }
        }

        float ig = 1.f / (1.f + __expf(-g0));
        float fg = 1.f / (1.f + __expf(-g1));
        float gg = tanhf(g2);
        float og = 1.f / (1.f + __expf(-g3));
        c_state = fg * c_state + ig * gg;
        float h = og * tanhf(c_state);

        g_hbuf[half][step & 1][bsel*Hn + u] = h;
        if (tpos < len) pooled += h;

        named_bar(barid);                 // this half's h stores all issued
        if (htid == 0)
            asm volatile("st.release.gpu.global.u32 [%0], %1;"
                         :: "l"(my_flag), "r"((unsigned)(step + 1)) : "memory");
    }
    g_pooled[bsel*G2 + half*Hn + u] = pooled;
}

// ---------------- kernel 3: FC layer GEMM (unchanged) ----------------
__global__ void __launch_bounds__(256,1) fc_kernel(
    const float* __restrict__ X, const float* __restrict__ W,
    const float* __restrict__ bias, const int* __restrict__ lenp,
    float* __restrict__ out, int K, int kshift, int N, int dorelu)
{
    extern __shared__ __align__(16) float fsm[];
    int KP = K + 2;
    float* Xs = fsm;
    float* Ws = fsm + 64*KP;
    int tid = threadIdx.x;
    int jt = blockIdx.x;

    for (int i = tid; i < 64*K; i += 256) {
        int b = i >> kshift, k = i & (K-1);
        Xs[b*KP + k] = X[i];
    }
    for (int i = tid; i < 16*K; i += 256) {
        int jl = i >> kshift, k = i & (K-1);
        int j = jt*16 + jl;
        Ws[jl*KP + k] = (j < N) ? W[(size_t)j*K + k] : 0.f;
    }
    __syncthreads();

    int bl = tid & 15, jl = tid >> 4;
    int j = jt*16 + jl;
    if (j >= N) return;

    ull acc[4];
    #pragma unroll
    for (int q = 0; q < 4; q++) acc[q] = 0ull;
    const float* wrow = &Ws[jl*KP];
    #pragma unroll 4
    for (int k = 0; k < K; k += 2) {
        ull wp = *(const ull*)(wrow + k);
        #pragma unroll
        for (int q = 0; q < 4; q++) {
            ull xpr = *(const ull*)(&Xs[(bl + 16*q)*KP + k]);
            fma2(acc[q], xpr, wp);
        }
    }
    #pragma unroll
    for (int q = 0; q < 4; q++) {
        int b = bl + 16*q;
        float bscale = lenp ? (float)lenp[b] : 1.f;
        float v = hadd2(acc[q]) + bias[j] * bscale;
        if (dorelu) v = fmaxf(v, 0.f);
        out[b*N + j] = v;
    }
}

// ---------------- host entry ----------------
extern "C" void kernel_launch(void* const* d_in, const int* in_sizes, int n_in,
                              void* d_out, int out_size)
{
    const int*   sentence = (const int*)d_in[0];
    const int*   text_len = (const int*)d_in[4];
    const float* emb  = (const float*)d_in[10];
    const float* wihf = (const float*)d_in[11];
    const float* whhf = (const float*)d_in[12];
    const float* bihf = (const float*)d_in[13];
    const float* bhhf = (const float*)d_in[14];
    const float* wihb = (const float*)d_in[15];
    const float* whhb = (const float*)d_in[16];
    const float* bihb = (const float*)d_in[17];
    const float* bhhb = (const float*)d_in[18];
    const float* gatw = (const float*)d_in[19];
    const float* gatb = (const float*)d_in[20];
    const float* fc1w = (const float*)d_in[21];
    const float* fc1b = (const float*)d_in[22];
    const float* fc2w = (const float*)d_in[23];
    const float* fc2b = (const float*)d_in[24];
    const float* fcfw = (const float*)d_in[25];
    const float* fcfb = (const float*)d_in[26];
    float* out = (float*)d_out;

    // 2 * (32*264 + 16*260) floats = 100,864 B
    const int recur_smem = 2 * (32*WHH_S + 16*H_S) * 4;
    cudaFuncSetAttribute(recur_kernel, cudaFuncAttributeMaxDynamicSharedMemorySize, recur_smem);
    const int fc_smem512 = 80 * 514 * 4;
    const int fc_smem256 = 80 * 258 * 4;
    cudaFuncSetAttribute(fc_kernel, cudaFuncAttributeMaxDynamicSharedMemorySize, fc_smem512);

    void *p_pooled, *p_a0, *p_a1;
    cudaGetSymbolAddress(&p_pooled, g_pooled);
    cudaGetSymbolAddress(&p_a0, g_act0);
    cudaGetSymbolAddress(&p_a1, g_act1);

    // launch order places recur_kernel 4th -> it lands in the ncu capture window
    proj_kernel<<<dim3(16, 64), 256>>>(sentence, emb, wihf, wihb, bihf, bhhf, bihb, bhhb);
    reset_kernel<<<1, 256>>>();
    pad_kernel<<<1, 32>>>();
    recur_kernel<<<128, 256, recur_smem>>>(whhf, whhb, text_len);
    fc_kernel<<<32, 256, fc_smem512>>>((const float*)p_pooled, gatw, gatb, text_len,
                                       (float*)p_a0, 512, 9, 512, 1);
    fc_kernel<<<16, 256, fc_smem512>>>((const float*)p_a0, fc1w, fc1b, nullptr,
                                       (float*)p_a1, 512, 9, 256, 1);
    fc_kernel<<<16, 256, fc_smem256>>>((const float*)p_a1, fc2w, fc2b, nullptr,
                                       (float*)p_a0, 256, 8, 256, 1);
    fc_kernel<<<1, 256, fc_smem256>>> ((const float*)p_a0, fcfw, fcfb, nullptr,
                                       out, 256, 8, 2, 0);
}

// round 16
// speedup vs baseline: 1.9220x; 1.9220x over previous
#include <cuda_runtime.h>
#include <math.h>

typedef unsigned long long ull;

#define Bn  64
#define Tn  128
#define En  300
#define Hn  256
#define G4  1024
#define G2  512
#define WHH_S 264     // w row stride: 2 khalf blocks of 132 floats
#define H_S   260     // h row stride

// ---------------- device scratch ----------------
__device__ float g_xproj[2][(size_t)Bn*Tn*G4];   // [dir][(b*T+t)*1024 + u*4 + gate]
__device__ float g_hbuf[2][2][Bn*Hn];            // [dir][parity][b*256 + u]
__device__ float g_pooled[Bn*G2];
__device__ float g_act0[Bn*G2];
__device__ float g_act1[Bn*G2];
__device__ __align__(128) unsigned g_flags[2][4][32];  // one 128B line per (dir,bq)

// ---------------- packed f32x2 helpers ----------------
__device__ __forceinline__ void fma2(ull& d, ull a, ull b){
    asm("fma.rn.f32x2 %0, %1, %2, %0;" : "+l"(d) : "l"(a), "l"(b));
}
__device__ __forceinline__ float hadd2(ull v){
    float a, b;
    asm("mov.b64 {%0, %1}, %2;" : "=f"(a), "=f"(b) : "l"(v));
    return a + b;
}
__device__ __forceinline__ ull pack2(float lo, float hi){
    ull r;
    asm("mov.b64 %0, {%1, %2};" : "=l"(r) : "f"(lo), "f"(hi));
    return r;
}
__device__ __forceinline__ void unpack2(float& lo, float& hi, ull v){
    asm("mov.b64 {%0, %1}, %2;" : "=f"(lo), "=f"(hi) : "l"(v));
}
__device__ __forceinline__ void ldsv2(ull& a, ull& b, unsigned addr){
    asm volatile("ld.shared.v2.b64 {%0, %1}, [%2];" : "=l"(a), "=l"(b) : "r"(addr));
}
__device__ __forceinline__ void named_bar(int id){
    asm volatile("bar.sync %0, 128;" :: "r"(id) : "memory");
}

// ---------------- tiny kernels: reset + pad (launch-order shim for ncu) ----------------
__global__ void reset_kernel(){
    if (threadIdx.x < 2*4*32)
        ((unsigned*)g_flags)[threadIdx.x] = 0u;
}
__global__ void pad_kernel(){}

// ---------------- kernel 1: gathered input projection GEMM (unchanged) ----------------
__global__ void __launch_bounds__(256,2) proj_kernel(
    const int* __restrict__ sentence, const float* __restrict__ emb,
    const float* __restrict__ wf, const float* __restrict__ wb,
    const float* __restrict__ bihf, const float* __restrict__ bhhf,
    const float* __restrict__ bihb, const float* __restrict__ bhhb)
{
    __shared__ __align__(16) float Asm[32*130];
    __shared__ __align__(16) float Bsm[32*130];
    __shared__ int tok[128];
    int tid = threadIdx.x;
    int rowbase = blockIdx.y * 128;
    int colbase = blockIdx.x * 128;
    int dir = colbase >> 10;
    const float* wsrc = dir ? wb : wf;
    if (tid < 128) tok[tid] = sentence[rowbase + tid];
    __syncthreads();

    int tx = tid & 15, ty = tid >> 4;
    ull acc[4][8];
    #pragma unroll
    for (int i = 0; i < 4; i++)
        #pragma unroll
        for (int m = 0; m < 8; m++) acc[i][m] = 0ull;

    for (int k0 = 0; k0 < 320; k0 += 32) {
        #pragma unroll
        for (int it = 0; it < 16; ++it) {
            int idx = tid + it * 256;
            int kk = idx & 31, r = idx >> 5;
            int k = k0 + kk;
            Asm[kk*130 + r] = (k < En) ? emb[(size_t)tok[r] * En + k] : 0.f;
        }
        #pragma unroll
        for (int it = 0; it < 16; ++it) {
            int idx = tid + it * 256;
            int kk = idx & 31, j = idx >> 5;
            int k = k0 + kk;
            int jg = (colbase + j) & 1023;
            Bsm[kk*130 + j] = (k < En) ? wsrc[jg * En + k] : 0.f;
        }
        __syncthreads();
        #pragma unroll 4
        for (int kk = 0; kk < 32; ++kk) {
            const float* arow = &Asm[kk*130 + ty*8];
            const float* brow = &Bsm[kk*130 + tx];
            ull ap[4];
            #pragma unroll
            for (int i = 0; i < 4; i++) ap[i] = *(const ull*)(arow + 2*i);
            #pragma unroll
            for (int m = 0; m < 8; m++) {
                float bv = brow[m*16];
                ull bb = pack2(bv, bv);
                #pragma unroll
                for (int i = 0; i < 4; i++) fma2(acc[i][m], ap[i], bb);
            }
        }
        __syncthreads();
    }
    const float* bih = dir ? bihb : bihf;
    const float* bhh = dir ? bhhb : bhhf;
    float* outp = g_xproj[dir];
    #pragma unroll
    for (int m = 0; m < 8; m++) {
        int jg = (colbase + tx + m*16) & 1023;
        int u = jg & 255, g = jg >> 8;
        float bsum = bih[jg] + bhh[jg];
        #pragma unroll
        for (int i = 0; i < 4; i++) {
            float lo, hi;
            unpack2(lo, hi, acc[i][m]);
            int r0 = rowbase + ty*8 + 2*i;
            outp[(size_t)r0 * G4 + u*4 + g]       = lo + bsum;
            outp[(size_t)(r0+1) * G4 + u*4 + g]   = hi + bsum;
        }
    }
}

// ---------------- kernel 2: dual-direction BiLSTM recurrence ----------------
// 128 blocks = bq(4) x ubk(32). Threads 0-127: dir0, 128-255: dir1.
// Sync per (dir,bq): 32 per-block flags in one 128B line. Producer posts
// step+1 via st.release to its OWN word (parallel, no atomic drain).
// ONLY warp 0 of each half polls the line (lane i -> word i, __all_sync);
// the other 3 warps park on the named barrier (R15 lesson: all-warp global
// polling floods LSU/L2 and regresses 2.3x).
__global__ void __launch_bounds__(256,1) recur_kernel(
    const float* __restrict__ whh_f, const float* __restrict__ whh_b,
    const int* __restrict__ text_len)
{
    extern __shared__ __align__(16) float dyn[];
    // layout per half: w_sm[32*264], h_sm[16*260]
    int bx  = blockIdx.x;
    int bq  = bx >> 5;
    int ubk = bx & 31;               // units ubk*8 .. +7
    int tid = threadIdx.x;
    int half = tid >> 7;             // dir
    int htid = tid & 127;
    int lane = tid & 31;
    int bl    = htid & 7;
    int khalf = (htid >> 3) & 1;
    int ul    = htid >> 4;           // 0..7
    int bsel = bq*16 + bl + khalf*8; // owned batch
    int u = ubk*8 + ul;

    float* wsm = dyn + half * (32*WHH_S);
    float* hsm = dyn + 2*(32*WHH_S) + half * (16*H_S);

    const float* whh = half ? whh_b : whh_f;
    // stage w rows (8 units x 4 gates) x 256, khalf-blocked: [r][kh*132 + kk]
    #pragma unroll 2
    for (int r = 0; r < 32; ++r) {
        int ul2 = r >> 2, g = r & 3;
        for (int k = htid; k < Hn; k += 128) {
            int kh = k >> 7, kk = k & 127;
            wsm[r*WHH_S + kh*132 + kk] = whh[(size_t)(g*Hn + ubk*8 + ul2) * Hn + k];
        }
    }
    __syncthreads();

    unsigned h0_addr = (unsigned)__cvta_generic_to_shared(hsm + bl*H_S       + khalf*128);
    unsigned h1_addr = (unsigned)__cvta_generic_to_shared(hsm + (bl+8)*H_S   + khalf*128);
    unsigned w_addr  = (unsigned)__cvta_generic_to_shared(wsm + (ul*4)*WHH_S + khalf*132);

    float c_state = 0.f, pooled = 0.f;
    int len = text_len[bsel];
    const float* xp = g_xproj[half];
    unsigned* flag_line = &g_flags[half][bq][0];      // 32 words, one line
    unsigned* my_flag   = &g_flags[half][bq][ubk];
    int barid = 1 + half;

    for (int step = 0; step < Tn; ++step) {
        int tpos = half ? (Tn - 1 - step) : step;
        float4 gx = *(const float4*)(xp + ((size_t)bsel*Tn + tpos)*G4 + u*4);
        float g0 = gx.x, g1 = gx.y, g2 = gx.z, g3 = gx.w;

        if (step > 0) {
            // ---- warp 0 of this half polls all 32 group flags ----
            if ((htid >> 5) == 0) {
                unsigned v;
                do {
                    asm volatile("ld.acquire.gpu.global.u32 %0, [%1];"
                                 : "=r"(v) : "l"(flag_line + lane) : "memory");
                } while (!__all_sync(0xffffffffu, v >= (unsigned)step));
            }
            named_bar(barid);
            // ---- copy this half's 16 h rows (16 x 256) into smem ----
            const float* hsrc = g_hbuf[half][(step + 1) & 1] + (size_t)bq*16*Hn;
            #pragma unroll
            for (int q = 0; q < 8; q++) {
                int idx = htid + q*128;
                int row = idx >> 6, c4 = idx & 63;
                float4 vv = __ldcg((const float4*)(hsrc + row*Hn + c4*4));
                *(float4*)&hsm[row*H_S + c4*4] = vv;
            }
            named_bar(barid);
            // ---- partial gate dots: 2 batches x 4 gates over 128 k ----
            ull accA[4][2], accB[4][2];
            #pragma unroll
            for (int g = 0; g < 4; g++) {
                accA[g][0] = accA[g][1] = 0ull;
                accB[g][0] = accB[g][1] = 0ull;
            }
            #pragma unroll 8
            for (int kk = 0; kk < 128; kk += 4) {
                ull ha0, ha1, hb0, hb1;
                ldsv2(ha0, ha1, h0_addr + kk*4);
                ldsv2(hb0, hb1, h1_addr + kk*4);
                #pragma unroll
                for (int g = 0; g < 4; g++) {
                    ull w01, w23;
                    ldsv2(w01, w23, w_addr + (unsigned)(g*WHH_S*4) + kk*4);
                    fma2(accA[g][0], w01, ha0); fma2(accA[g][1], w23, ha1);
                    fma2(accB[g][0], w01, hb0); fma2(accB[g][1], w23, hb1);
                }
            }
            // ---- combine khalf partials: own batch + partner's other-batch ----
            #pragma unroll
            for (int g = 0; g < 4; g++) {
                float sA = hadd2(accA[g][0]) + hadd2(accA[g][1]);   // batch bl
                float sB = hadd2(accB[g][0]) + hadd2(accB[g][1]);   // batch bl+8
                float own = khalf ? sB : sA;
                float oth = khalf ? sA : sB;
                float full = own + __shfl_xor_sync(0xffffffffu, oth, 8);
                if (g == 0) g0 += full;
                else if (g == 1) g1 += full;
                else if (g == 2) g2 += full;
                else g3 += full;
            }
        }

        float ig = 1.f / (1.f + __expf(-g0));
        float fg = 1.f / (1.f + __expf(-g1));
        float gg = tanhf(g2);
        float og = 1.f / (1.f + __expf(-g3));
        c_state = fg * c_state + ig * gg;
        float h = og * tanhf(c_state);

        g_hbuf[half][step & 1][bsel*Hn + u] = h;
        if (tpos < len) pooled += h;

        named_bar(barid);                 // this half's h stores all issued
        if (htid == 0)
            asm volatile("st.release.gpu.global.u32 [%0], %1;"
                         :: "l"(my_flag), "r"((unsigned)(step + 1)) : "memory");
    }
    g_pooled[bsel*G2 + half*Hn + u] = pooled;
}

// ---------------- kernel 3: FC layer GEMM (unchanged) ----------------
__global__ void __launch_bounds__(256,1) fc_kernel(
    const float* __restrict__ X, const float* __restrict__ W,
    const float* __restrict__ bias, const int* __restrict__ lenp,
    float* __restrict__ out, int K, int kshift, int N, int dorelu)
{
    extern __shared__ __align__(16) float fsm[];
    int KP = K + 2;
    float* Xs = fsm;
    float* Ws = fsm + 64*KP;
    int tid = threadIdx.x;
    int jt = blockIdx.x;

    for (int i = tid; i < 64*K; i += 256) {
        int b = i >> kshift, k = i & (K-1);
        Xs[b*KP + k] = X[i];
    }
    for (int i = tid; i < 16*K; i += 256) {
        int jl = i >> kshift, k = i & (K-1);
        int j = jt*16 + jl;
        Ws[jl*KP + k] = (j < N) ? W[(size_t)j*K + k] : 0.f;
    }
    __syncthreads();

    int bl = tid & 15, jl = tid >> 4;
    int j = jt*16 + jl;
    if (j >= N) return;

    ull acc[4];
    #pragma unroll
    for (int q = 0; q < 4; q++) acc[q] = 0ull;
    const float* wrow = &Ws[jl*KP];
    #pragma unroll 4
    for (int k = 0; k < K; k += 2) {
        ull wp = *(const ull*)(wrow + k);
        #pragma unroll
        for (int q = 0; q < 4; q++) {
            ull xpr = *(const ull*)(&Xs[(bl + 16*q)*KP + k]);
            fma2(acc[q], xpr, wp);
        }
    }
    #pragma unroll
    for (int q = 0; q < 4; q++) {
        int b = bl + 16*q;
        float bscale = lenp ? (float)lenp[b] : 1.f;
        float v = hadd2(acc[q]) + bias[j] * bscale;
        if (dorelu) v = fmaxf(v, 0.f);
        out[b*N + j] = v;
    }
}

// ---------------- host entry ----------------
extern "C" void kernel_launch(void* const* d_in, const int* in_sizes, int n_in,
                              void* d_out, int out_size)
{
    const int*   sentence = (const int*)d_in[0];
    const int*   text_len = (const int*)d_in[4];
    const float* emb  = (const float*)d_in[10];
    const float* wihf = (const float*)d_in[11];
    const float* whhf = (const float*)d_in[12];
    const float* bihf = (const float*)d_in[13];
    const float* bhhf = (const float*)d_in[14];
    const float* wihb = (const float*)d_in[15];
    const float* whhb = (const float*)d_in[16];
    const float* bihb = (const float*)d_in[17];
    const float* bhhb = (const float*)d_in[18];
    const float* gatw = (const float*)d_in[19];
    const float* gatb = (const float*)d_in[20];
    const float* fc1w = (const float*)d_in[21];
    const float* fc1b = (const float*)d_in[22];
    const float* fc2w = (const float*)d_in[23];
    const float* fc2b = (const float*)d_in[24];
    const float* fcfw = (const float*)d_in[25];
    const float* fcfb = (const float*)d_in[26];
    float* out = (float*)d_out;

    // 2 * (32*264 + 16*260) floats = 100,864 B
    const int recur_smem = 2 * (32*WHH_S + 16*H_S) * 4;
    cudaFuncSetAttribute(recur_kernel, cudaFuncAttributeMaxDynamicSharedMemorySize, recur_smem);
    const int fc_smem512 = 80 * 514 * 4;
    const int fc_smem256 = 80 * 258 * 4;
    cudaFuncSetAttribute(fc_kernel, cudaFuncAttributeMaxDynamicSharedMemorySize, fc_smem512);

    void *p_pooled, *p_a0, *p_a1;
    cudaGetSymbolAddress(&p_pooled, g_pooled);
    cudaGetSymbolAddress(&p_a0, g_act0);
    cudaGetSymbolAddress(&p_a1, g_act1);

    // launch order places recur_kernel 4th -> it lands in the ncu capture window
    proj_kernel<<<dim3(16, 64), 256>>>(sentence, emb, wihf, wihb, bihf, bhhf, bihb, bhhb);
    reset_kernel<<<1, 256>>>();
    pad_kernel<<<1, 32>>>();
    recur_kernel<<<128, 256, recur_smem>>>(whhf, whhb, text_len);
    fc_kernel<<<32, 256, fc_smem512>>>((const float*)p_pooled, gatw, gatb, text_len,
                                       (float*)p_a0, 512, 9, 512, 1);
    fc_kernel<<<16, 256, fc_smem512>>>((const float*)p_a0, fc1w, fc1b, nullptr,
                                       (float*)p_a1, 512, 9, 256, 1);
    fc_kernel<<<16, 256, fc_smem256>>>((const float*)p_a1, fc2w, fc2b, nullptr,
                                       (float*)p_a0, 256, 8, 256, 1);
    fc_kernel<<<1, 256, fc_smem256>>> ((const float*)p_a0, fcfw, fcfb, nullptr,
                                       out, 256, 8, 2, 0);
}

// round 17
// speedup vs baseline: 2.8111x; 1.4626x over previous
#include <cuda_runtime.h>
#include <math.h>

typedef unsigned long long ull;

#define Bn  64
#define Tn  128
#define En  300
#define Hn  256
#define G4  1024
#define G2  512
#define H_S 260                 // h row stride (floats)
#define HALF_SM (8*H_S + 2048)  // per-half smem floats: h[8][260] + partials[2048]

// ---------------- device scratch ----------------
__device__ float g_xproj[2][(size_t)Bn*Tn*G4];   // [dir][(b*T+t)*1024 + u*4 + gate]
__device__ float g_hbuf[2][2][Bn*Hn];            // [dir][parity][b*256 + u]
__device__ float g_pooled[Bn*G2];
__device__ float g_act0[Bn*G2];
__device__ float g_act1[Bn*G2];
__device__ unsigned g_cnt[2][8][32];             // [dir][bq][pad] -> 128B apart

// ---------------- packed f32x2 helpers ----------------
__device__ __forceinline__ void fma2(ull& d, ull a, ull b){
    asm("fma.rn.f32x2 %0, %1, %2, %0;" : "+l"(d) : "l"(a), "l"(b));
}
__device__ __forceinline__ float hadd2(ull v){
    float a, b;
    asm("mov.b64 {%0, %1}, %2;" : "=f"(a), "=f"(b) : "l"(v));
    return a + b;
}
__device__ __forceinline__ ull pack2(float lo, float hi){
    ull r;
    asm("mov.b64 %0, {%1, %2};" : "=l"(r) : "f"(lo), "f"(hi));
    return r;
}
__device__ __forceinline__ void unpack2(float& lo, float& hi, ull v){
    asm("mov.b64 {%0, %1}, %2;" : "=f"(lo), "=f"(hi) : "l"(v));
}
__device__ __forceinline__ void ldsv2(ull& a, ull& b, unsigned addr){
    asm volatile("ld.shared.v2.b64 {%0, %1}, [%2];" : "=l"(a), "=l"(b) : "r"(addr));
}
__device__ __forceinline__ void named_bar(int id){
    asm volatile("bar.sync %0, 128;" :: "r"(id) : "memory");
}

// ---------------- tiny kernels: reset + pad (launch-order shim for ncu) ----------------
__global__ void reset_kernel(){
    for (int i = threadIdx.x; i < 2*8*32; i += blockDim.x)
        ((unsigned*)g_cnt)[i] = 0u;
}
__global__ void pad_kernel(){}

// ---------------- kernel 1: gathered input projection GEMM (unchanged) ----------------
__global__ void __launch_bounds__(256,2) proj_kernel(
    const int* __restrict__ sentence, const float* __restrict__ emb,
    const float* __restrict__ wf, const float* __restrict__ wb,
    const float* __restrict__ bihf, const float* __restrict__ bhhf,
    const float* __restrict__ bihb, const float* __restrict__ bhhb)
{
    __shared__ __align__(16) float Asm[32*130];
    __shared__ __align__(16) float Bsm[32*130];
    __shared__ int tok[128];
    int tid = threadIdx.x;
    int rowbase = blockIdx.y * 128;
    int colbase = blockIdx.x * 128;
    int dir = colbase >> 10;
    const float* wsrc = dir ? wb : wf;
    if (tid < 128) tok[tid] = sentence[rowbase + tid];
    __syncthreads();

    int tx = tid & 15, ty = tid >> 4;
    ull acc[4][8];
    #pragma unroll
    for (int i = 0; i < 4; i++)
        #pragma unroll
        for (int m = 0; m < 8; m++) acc[i][m] = 0ull;

    for (int k0 = 0; k0 < 320; k0 += 32) {
        #pragma unroll
        for (int it = 0; it < 16; ++it) {
            int idx = tid + it * 256;
            int kk = idx & 31, r = idx >> 5;
            int k = k0 + kk;
            Asm[kk*130 + r] = (k < En) ? emb[(size_t)tok[r] * En + k] : 0.f;
        }
        #pragma unroll
        for (int it = 0; it < 16; ++it) {
            int idx = tid + it * 256;
            int kk = idx & 31, j = idx >> 5;
            int k = k0 + kk;
            int jg = (colbase + j) & 1023;
            Bsm[kk*130 + j] = (k < En) ? wsrc[jg * En + k] : 0.f;
        }
        __syncthreads();
        #pragma unroll 4
        for (int kk = 0; kk < 32; ++kk) {
            const float* arow = &Asm[kk*130 + ty*8];
            const float* brow = &Bsm[kk*130 + tx];
            ull ap[4];
            #pragma unroll
            for (int i = 0; i < 4; i++) ap[i] = *(const ull*)(arow + 2*i);
            #pragma unroll
            for (int m = 0; m < 8; m++) {
                float bv = brow[m*16];
                ull bb = pack2(bv, bv);
                #pragma unroll
                for (int i = 0; i < 4; i++) fma2(acc[i][m], ap[i], bb);
            }
        }
        __syncthreads();
    }
    const float* bih = dir ? bihb : bihf;
    const float* bhh = dir ? bhhb : bhhf;
    float* outp = g_xproj[dir];
    #pragma unroll
    for (int m = 0; m < 8; m++) {
        int jg = (colbase + tx + m*16) & 1023;
        int u = jg & 255, g = jg >> 8;
        float bsum = bih[jg] + bhh[jg];
        #pragma unroll
        for (int i = 0; i < 4; i++) {
            float lo, hi;
            unpack2(lo, hi, acc[i][m]);
            int r0 = rowbase + ty*8 + 2*i;
            outp[(size_t)r0 * G4 + u*4 + g]       = lo + bsum;
            outp[(size_t)(r0+1) * G4 + u*4 + g]   = hi + bsum;
        }
    }
}

// ---------------- kernel 2: BiLSTM recurrence, w-in-registers ----------------
// 128 blocks = bq(8) x ubk(16). Threads 0-127: dir0, 128-255: dir1.
// Per half: 4 warps = 4 k-segments (64 k each). Lane = g(4) x up(8); lane holds
// w[g][ubk*16+up] and w[g][ubk*16+up+8] over its 64-k segment in REGISTERS.
// Inner loop: broadcast h (1 wavefront per LDS) x register w -> fma-bound.
// k-segment partials -> smem -> activation phase mapped (u16 x b8).
// Sync: R14-proven per-(dir,bq) atomic counter, 16 arrivals/step.
__global__ void __launch_bounds__(256,1) recur_kernel(
    const float* __restrict__ whh_f, const float* __restrict__ whh_b,
    const int* __restrict__ text_len)
{
    extern __shared__ __align__(16) float dyn[];
    int bx  = blockIdx.x;
    int bq  = bx >> 4;               // 0..7  (8 batches each)
    int ubk = bx & 15;               // 0..15 (16 units each)
    int tid = threadIdx.x;
    int half = tid >> 7;             // dir
    int htid = tid & 127;
    int ks   = htid >> 5;            // warp = k-segment 0..3
    int lane = htid & 31;
    int g  = lane >> 3, up = lane & 7;      // compute role
    int au = htid >> 3, ab = htid & 7;      // activation role: u 0..15, b 0..7
    int bsel  = bq*8 + ab;
    int uglob = ubk*16 + au;

    float* hsm = dyn + half * HALF_SM;          // h[8][260]
    float* psm = hsm + 8*H_S;                   // partials [ks4][g4][u16][b8]

    // ---- load w into registers: rows (g*Hn + ubk*16 + up[+8]), cols ks*64..+63 ----
    const float* whh = half ? whh_b : whh_f;
    ull w0[32], w1[32];
    {
        const ull* s0 = (const ull*)(whh + (size_t)(g*Hn + ubk*16 + up    )*Hn + ks*64);
        const ull* s1 = (const ull*)(whh + (size_t)(g*Hn + ubk*16 + up + 8)*Hn + ks*64);
        #pragma unroll
        for (int i = 0; i < 32; i++) { w0[i] = s0[i]; w1[i] = s1[i]; }
    }

    unsigned hbase = (unsigned)__cvta_generic_to_shared(hsm) + (unsigned)(ks*64*4);

    float c_state = 0.f, pooled = 0.f;
    int len = text_len[bsel];
    const float* xp = g_xproj[half];
    unsigned* cnt = &g_cnt[half][bq][0];
    int barid = 1 + half;

    for (int step = 0; step < Tn; ++step) {
        int tpos = half ? (Tn - 1 - step) : step;
        // activation-role gate preload (issued early; latency hidden by compute)
        float4 gx = *(const float4*)(xp + ((size_t)bsel*Tn + tpos)*G4 + uglob*4);
        float g0 = gx.x, g1 = gx.y, g2 = gx.z, g3 = gx.w;

        if (step > 0) {
            // ---- per-(dir,bq) wait: 16 producer block-halves arrived ----
            if (htid == 0) {
                unsigned tgt = 16u * (unsigned)step;
                unsigned v;
                do {
                    asm volatile("ld.acquire.gpu.global.u32 %0, [%1];"
                                 : "=r"(v) : "l"(cnt) : "memory");
                } while (v < tgt);
            }
            named_bar(barid);
            // ---- copy this half's 8 h rows (8 x 256) into smem ----
            const float* hsrc = g_hbuf[half][(step + 1) & 1] + (size_t)bq*8*Hn;
            #pragma unroll
            for (int q = 0; q < 4; q++) {
                int idx = htid + q*128;              // 0..511 float4 chunks
                int row = idx >> 6, c4 = idx & 63;
                float4 vv = __ldcg((const float4*)(hsrc + row*Hn + c4*4));
                *(float4*)&hsm[row*H_S + c4*4] = vv;
            }
            named_bar(barid);
            // ---- compute partials: 8 batches x 2 outputs over this 64-k segment ----
            float part0[8], part1[8];
            #pragma unroll
            for (int b = 0; b < 8; b++) {
                ull a0=0, a1=0, c0=0, c1=0;
                unsigned hb = hbase + (unsigned)(b*H_S*4);
                #pragma unroll
                for (int kk = 0; kk < 64; kk += 4) {
                    ull h01, h23;
                    ldsv2(h01, h23, hb + kk*4);      // broadcast: all lanes same addr
                    fma2(a0, w0[kk>>1], h01); fma2(a1, w0[(kk>>1)+1], h23);
                    fma2(c0, w1[kk>>1], h01); fma2(c1, w1[(kk>>1)+1], h23);
                }
                part0[b] = hadd2(a0) + hadd2(a1);
                part1[b] = hadd2(c0) + hadd2(c1);
            }
            // ---- write partials: p[((ks*4+g)*16+u)*8 + b] ----
            float4* pp0 = (float4*)&psm[((ks*4+g)*16 + up    )*8];
            float4* pp1 = (float4*)&psm[((ks*4+g)*16 + up + 8)*8];
            pp0[0] = make_float4(part0[0], part0[1], part0[2], part0[3]);
            pp0[1] = make_float4(part0[4], part0[5], part0[6], part0[7]);
            pp1[0] = make_float4(part1[0], part1[1], part1[2], part1[3]);
            pp1[1] = make_float4(part1[4], part1[5], part1[6], part1[7]);
            named_bar(barid);
            // ---- activation role: sum 4 ksegs x 4 gates ----
            #pragma unroll
            for (int k2 = 0; k2 < 4; k2++) {
                g0 += psm[((k2*4 + 0)*16 + au)*8 + ab];
                g1 += psm[((k2*4 + 1)*16 + au)*8 + ab];
                g2 += psm[((k2*4 + 2)*16 + au)*8 + ab];
                g3 += psm[((k2*4 + 3)*16 + au)*8 + ab];
            }
        }

        float ig = 1.f / (1.f + __expf(-g0));
        float fg = 1.f / (1.f + __expf(-g1));
        float gg = tanhf(g2);
        float og = 1.f / (1.f + __expf(-g3));
        c_state = fg * c_state + ig * gg;
        float h = og * tanhf(c_state);

        g_hbuf[half][step & 1][bsel*Hn + uglob] = h;
        if (tpos < len) pooled += h;

        named_bar(barid);                 // this half's h stores + psm reads done
        if (htid == 0)
            asm volatile("red.release.gpu.global.add.u32 [%0], 1;"
                         :: "l"(cnt) : "memory");
    }
    g_pooled[bsel*G2 + half*Hn + uglob] = pooled;
}

// ---------------- kernel 3: FC layer GEMM (unchanged) ----------------
__global__ void __launch_bounds__(256,1) fc_kernel(
    const float* __restrict__ X, const float* __restrict__ W,
    const float* __restrict__ bias, const int* __restrict__ lenp,
    float* __restrict__ out, int K, int kshift, int N, int dorelu)
{
    extern __shared__ __align__(16) float fsm[];
    int KP = K + 2;
    float* Xs = fsm;
    float* Ws = fsm + 64*KP;
    int tid = threadIdx.x;
    int jt = blockIdx.x;

    for (int i = tid; i < 64*K; i += 256) {
        int b = i >> kshift, k = i & (K-1);
        Xs[b*KP + k] = X[i];
    }
    for (int i = tid; i < 16*K; i += 256) {
        int jl = i >> kshift, k = i & (K-1);
        int j = jt*16 + jl;
        Ws[jl*KP + k] = (j < N) ? W[(size_t)j*K + k] : 0.f;
    }
    __syncthreads();

    int bl = tid & 15, jl = tid >> 4;
    int j = jt*16 + jl;
    if (j >= N) return;

    ull acc[4];
    #pragma unroll
    for (int q = 0; q < 4; q++) acc[q] = 0ull;
    const float* wrow = &Ws[jl*KP];
    #pragma unroll 4
    for (int k = 0; k < K; k += 2) {
        ull wp = *(const ull*)(wrow + k);
        #pragma unroll
        for (int q = 0; q < 4; q++) {
            ull xpr = *(const ull*)(&Xs[(bl + 16*q)*KP + k]);
            fma2(acc[q], xpr, wp);
        }
    }
    #pragma unroll
    for (int q = 0; q < 4; q++) {
        int b = bl + 16*q;
        float bscale = lenp ? (float)lenp[b] : 1.f;
        float v = hadd2(acc[q]) + bias[j] * bscale;
        if (dorelu) v = fmaxf(v, 0.f);
        out[b*N + j] = v;
    }
}

// ---------------- host entry ----------------
extern "C" void kernel_launch(void* const* d_in, const int* in_sizes, int n_in,
                              void* d_out, int out_size)
{
    const int*   sentence = (const int*)d_in[0];
    const int*   text_len = (const int*)d_in[4];
    const float* emb  = (const float*)d_in[10];
    const float* wihf = (const float*)d_in[11];
    const float* whhf = (const float*)d_in[12];
    const float* bihf = (const float*)d_in[13];
    const float* bhhf = (const float*)d_in[14];
    const float* wihb = (const float*)d_in[15];
    const float* whhb = (const float*)d_in[16];
    const float* bihb = (const float*)d_in[17];
    const float* bhhb = (const float*)d_in[18];
    const float* gatw = (const float*)d_in[19];
    const float* gatb = (const float*)d_in[20];
    const float* fc1w = (const float*)d_in[21];
    const float* fc1b = (const float*)d_in[22];
    const float* fc2w = (const float*)d_in[23];
    const float* fc2b = (const float*)d_in[24];
    const float* fcfw = (const float*)d_in[25];
    const float* fcfb = (const float*)d_in[26];
    float* out = (float*)d_out;

    const int recur_smem = 2 * HALF_SM * 4;     // 2 * (2080+2048) * 4 = 33,024 B
    cudaFuncSetAttribute(recur_kernel, cudaFuncAttributeMaxDynamicSharedMemorySize, recur_smem);
    const int fc_smem512 = 80 * 514 * 4;
    const int fc_smem256 = 80 * 258 * 4;
    cudaFuncSetAttribute(fc_kernel, cudaFuncAttributeMaxDynamicSharedMemorySize, fc_smem512);

    void *p_pooled, *p_a0, *p_a1;
    cudaGetSymbolAddress(&p_pooled, g_pooled);
    cudaGetSymbolAddress(&p_a0, g_act0);
    cudaGetSymbolAddress(&p_a1, g_act1);

    // launch order places recur_kernel 4th -> it lands in the ncu capture window
    proj_kernel<<<dim3(16, 64), 256>>>(sentence, emb, wihf, wihb, bihf, bhhf, bihb, bhhb);
    reset_kernel<<<1, 256>>>();
    pad_kernel<<<1, 32>>>();
    recur_kernel<<<128, 256, recur_smem>>>(whhf, whhb, text_len);
    fc_kernel<<<32, 256, fc_smem512>>>((const float*)p_pooled, gatw, gatb, text_len,
                                       (float*)p_a0, 512, 9, 512, 1);
    fc_kernel<<<16, 256, fc_smem512>>>((const float*)p_a0, fc1w, fc1b, nullptr,
                                       (float*)p_a1, 512, 9, 256, 1);
    fc_kernel<<<16, 256, fc_smem256>>>((const float*)p_a1, fc2w, fc2b, nullptr,
                                       (float*)p_a0, 256, 8, 256, 1);
    fc_kernel<<<1, 256, fc_smem256>>> ((const float*)p_a0, fcfw, fcfb, nullptr,
                                       out, 256, 8, 2, 0);
}